// round 15
// baseline (speedup 1.0000x reference)
#include <cuda_runtime.h>
#include <cuda_fp16.h>
#include <cstdint>

#define N_NODES 8192
#define DIM 512

// ---------------- scratch (__device__ globals; no allocs allowed) ----------
__device__ float g_c[DIM];                                    // fused bias
__device__ float g_cpart[16 * DIM];                           // bias partials
__device__ __align__(16) __half g_xTq[DIM * N_NODES];         // [feat][node]
__device__ __align__(16) __half g_xq[N_NODES * DIM];          // [node][feat]
__device__ __align__(16) __half g_aggq[N_NODES * DIM];        // [node][feat]
__device__ __align__(16) __half g_ATq[DIM * DIM];             // (W_self@Wt)^T
__device__ __align__(16) __half g_BTq[DIM * DIM];             // (W_nb@Wb)^T

// ---------------- PTX helpers ----------------------------------------------
__device__ __forceinline__ uint32_t smem_u32(const void* p) {
    uint32_t a;
    asm("{ .reg .u64 t; cvta.to.shared.u64 t, %1; cvt.u32.u64 %0, t; }"
        : "=r"(a) : "l"(p));
    return a;
}
__device__ __forceinline__ void cp16(uint32_t dst, const void* src) {
    asm volatile("cp.async.cg.shared.global [%0], [%1], 16;"
                 :: "r"(dst), "l"(src) : "memory");
}
__device__ __forceinline__ void ldsm4(uint32_t& r0, uint32_t& r1, uint32_t& r2,
                                      uint32_t& r3, uint32_t addr) {
    asm volatile("ldmatrix.sync.aligned.m8n8.x4.shared.b16 {%0,%1,%2,%3}, [%4];"
                 : "=r"(r0), "=r"(r1), "=r"(r2), "=r"(r3) : "r"(addr));
}
__device__ __forceinline__ void mma_h(float* d, const uint32_t* a,
                                      const uint32_t& b0, const uint32_t& b1) {
    asm volatile(
        "mma.sync.aligned.m16n8k16.row.col.f32.f16.f16.f32 "
        "{%0,%1,%2,%3}, {%4,%5,%6,%7}, {%8,%9}, {%0,%1,%2,%3};"
        : "+f"(d[0]), "+f"(d[1]), "+f"(d[2]), "+f"(d[3])
        : "r"(a[0]), "r"(a[1]), "r"(a[2]), "r"(a[3]), "r"(b0), "r"(b1));
}
__device__ __forceinline__ uint32_t pack_h2(float a, float b) {
    __half2 h = __floats2half2_rn(a, b);
    return *(uint32_t*)&h;
}

// ---------------------------------------------------------------------------
// K0a: fused weights -> transposed fp16 (B-operand layout)
// ---------------------------------------------------------------------------
__global__ void fuse_weights_kernel(const float* __restrict__ W_self,
                                    const float* __restrict__ W_nb,
                                    const float* __restrict__ W_comb) {
    const int z = blockIdx.z;
    const float* __restrict__ Wx = z ? W_nb : W_self;
    __half* __restrict__ oq = z ? g_BTq : g_ATq;
    const int woff = z * DIM;

    __shared__ float As[16][64];
    __shared__ float Bs[16][64];
    const int tid = threadIdx.x;
    const int tx = tid & 15, ty = tid >> 4;
    const int brow = blockIdx.y * 64, bcol = blockIdx.x * 64;
    const int a_m = tid >> 2, a_kc = (tid & 3) << 2;
    const int b_k = tid >> 4, b_n = (tid & 15) << 2;

    float acc[4][4] = {};
    for (int k0 = 0; k0 < DIM; k0 += 16) {
        float4 av = *(const float4*)&Wx[(brow + a_m) * DIM + k0 + a_kc];
        As[a_kc + 0][a_m] = av.x; As[a_kc + 1][a_m] = av.y;
        As[a_kc + 2][a_m] = av.z; As[a_kc + 3][a_m] = av.w;
        *(float4*)&Bs[b_k][b_n] =
            *(const float4*)&W_comb[(woff + k0 + b_k) * DIM + bcol + b_n];
        __syncthreads();
        #pragma unroll
        for (int k = 0; k < 16; k++) {
            float af[4], bf[4];
            *(float4*)af = *(const float4*)&As[k][ty * 4];
            *(float4*)bf = *(const float4*)&Bs[k][tx * 4];
            #pragma unroll
            for (int i = 0; i < 4; i++)
                #pragma unroll
                for (int j = 0; j < 4; j++) acc[i][j] += af[i] * bf[j];
        }
        __syncthreads();
    }
    #pragma unroll
    for (int i = 0; i < 4; i++) {
        const int k = brow + ty * 4 + i;
        #pragma unroll
        for (int j = 0; j < 4; j++) {
            const int n = bcol + tx * 4 + j;
            oq[n * DIM + k] = __float2half_rn(acc[i][j]);
        }
    }
}

// ---------------------------------------------------------------------------
// K0b: fused bias — parallel partials + reduce
// ---------------------------------------------------------------------------
__global__ void fuse_bias_partial_kernel(const float* __restrict__ b_self,
                                         const float* __restrict__ b_nb,
                                         const float* __restrict__ W_comb) {
    const int p = blockIdx.x;
    const int j = threadIdx.x;
    const int k0 = p * 32;
    float s0 = 0.f, s1 = 0.f;
    #pragma unroll 8
    for (int k = k0; k < k0 + 32; k++) {
        s0 += b_self[k] * W_comb[k * DIM + j];
        s1 += b_nb[k] * W_comb[(DIM + k) * DIM + j];
    }
    g_cpart[p * DIM + j] = s0 + s1;
}

__global__ void fuse_bias_reduce_kernel(const float* __restrict__ b_comb) {
    const int j = threadIdx.x;
    float s = b_comb[j];
    #pragma unroll
    for (int p = 0; p < 16; p++) s += g_cpart[p * DIM + j];
    g_c[j] = s;
}

// ---------------------------------------------------------------------------
// K1b: x -> fp16 row-major + fp16 transposed
// ---------------------------------------------------------------------------
__global__ void transpose_split_kernel(const float* __restrict__ x) {
    __shared__ float t[32][33];
    const int c0 = blockIdx.x * 32;
    const int r0 = blockIdx.y * 32;
    const int tx = threadIdx.x, ty = threadIdx.y;
    #pragma unroll
    for (int i = 0; i < 4; i++) {
        const size_t gi = (size_t)(r0 + ty + 8 * i) * DIM + c0 + tx;
        float v = x[gi];
        t[ty + 8 * i][tx] = v;
        g_xq[gi] = __float2half_rn(v);
    }
    __syncthreads();
    #pragma unroll
    for (int i = 0; i < 4; i++) {
        float v = t[tx][ty + 8 * i];
        size_t o = (size_t)(c0 + ty + 8 * i) * N_NODES + r0 + tx;
        g_xTq[o] = __float2half_rn(v);
    }
}

// ---------------------------------------------------------------------------
// shared GEMM geometry
// ---------------------------------------------------------------------------
#define BK 32
#define PITCHB 80
#define TILEB (128 * PITCHB)      // 10240 B (128-row fp16 tile)

// ---------------------------------------------------------------------------
// K2: agg = (mask(adj) @ x) * recip, degree fused.  fp16 HMMA 64x64 warp tiles.
// BM=128, BN=256, 8 warps (2M x 4N), 4-stage ring, ONE barrier per chunk.
// Convert-one-ahead: during chunk s's MMA, int[s+1] -> fp16 A[s+1].
// ---------------------------------------------------------------------------
#define PITCHI 144                 // int tile pitch (128 B data + 16 pad)
#define I_TILE (128 * PITCHI)      // 18432 B
#define A_TILE (128 * PITCHB)      // 10240 B
#define B_TILE (256 * PITCHB)      // 20480 B
#define ASTAGE (I_TILE + A_TILE + B_TILE)  // 49152 B
#define AGG_SMEM (4 * ASTAGE)      // 196608 B

__device__ __forceinline__ void issue_stage_agg(uint32_t sb, const int* adj,
                                                int slot, int k0,
                                                int brow, int bcol, int tid) {
    const uint32_t base = sb + slot * ASTAGE;
    #pragma unroll
    for (int h = 0; h < 4; h++) {
        const int id = tid + h * 256;         // 0..1023
        const int row = id >> 3, seg = id & 7;
        cp16(base + row * PITCHI + seg * 16,
             adj + (size_t)(brow + row) * N_NODES + k0 + seg * 4);
    }
    const uint32_t bbase = base + I_TILE + A_TILE;
    #pragma unroll
    for (int h = 0; h < 4; h++) {
        const int bid = tid + h * 256;        // 0..1023
        const int row = bid >> 2, cc = bid & 3;
        cp16(bbase + row * PITCHB + cc * 16,
             g_xTq + (size_t)(bcol + row) * N_NODES + k0 + cc * 8);
    }
    asm volatile("cp.async.commit_group;" ::: "memory");
}

__device__ __forceinline__ void convert_stage(char* stage, int crow, int chalf,
                                              int& cnt) {
    int4 v[4];
    #pragma unroll
    for (int i = 0; i < 4; i++)
        v[i] = *(const int4*)(stage + crow * PITCHI + (chalf * 4 + i) * 16);
    #pragma unroll
    for (int i = 0; i < 4; i++)
        cnt += (v[i].x > 0) + (v[i].y > 0) + (v[i].z > 0) + (v[i].w > 0);
    uint4 o0, o1;
    o0.x = (v[0].x > 0 ? 0x3C00u : 0u) | ((v[0].y > 0 ? 0x3C00u : 0u) << 16);
    o0.y = (v[0].z > 0 ? 0x3C00u : 0u) | ((v[0].w > 0 ? 0x3C00u : 0u) << 16);
    o0.z = (v[1].x > 0 ? 0x3C00u : 0u) | ((v[1].y > 0 ? 0x3C00u : 0u) << 16);
    o0.w = (v[1].z > 0 ? 0x3C00u : 0u) | ((v[1].w > 0 ? 0x3C00u : 0u) << 16);
    o1.x = (v[2].x > 0 ? 0x3C00u : 0u) | ((v[2].y > 0 ? 0x3C00u : 0u) << 16);
    o1.y = (v[2].z > 0 ? 0x3C00u : 0u) | ((v[2].w > 0 ? 0x3C00u : 0u) << 16);
    o1.z = (v[3].x > 0 ? 0x3C00u : 0u) | ((v[3].y > 0 ? 0x3C00u : 0u) << 16);
    o1.w = (v[3].z > 0 ? 0x3C00u : 0u) | ((v[3].w > 0 ? 0x3C00u : 0u) << 16);
    char* adst = stage + I_TILE + crow * PITCHB + chalf * 32;
    *(uint4*)(adst) = o0;
    *(uint4*)(adst + 16) = o1;
}

__global__ void __launch_bounds__(256, 1) agg_mma_kernel(const int* __restrict__ adj) {
    extern __shared__ char smem[];
    const uint32_t sb = smem_u32(smem);
    char* smemc = smem;
    const int tid = threadIdx.x;
    const int lane = tid & 31, w = tid >> 5;
    const int wm = w & 1, wn = w >> 1;        // 2M x 4N warps, 64x64 each
    const int brow = blockIdx.y * 128;
    const int bcol = blockIdx.x * 256;
    const int g = lane >> 3, r = lane & 7;

    __shared__ float srecip[128];

    const int crow = tid >> 1, chalf = tid & 1;   // convert assignment
    int cnt = 0;                                  // degree (half-row)

    const int NIT = N_NODES / BK;  // 256
    issue_stage_agg(sb, adj, 0, 0, brow, bcol, tid);
    issue_stage_agg(sb, adj, 1, BK, brow, bcol, tid);
    issue_stage_agg(sb, adj, 2, 2 * BK, brow, bcol, tid);

    // prologue: convert chunk 0 (needs group 0 complete)
    asm volatile("cp.async.wait_group 2;" ::: "memory");
    __syncthreads();
    convert_stage(smemc, crow, chalf, cnt);

    float acc[4][8][4] = {};   // 4 m16 x 8 n8

    for (int s = 0; s < NIT; s++) {
        // groups <= s+1 complete (int[s+1], B[s] and earlier all arrived)
        asm volatile("cp.async.wait_group 1;" ::: "memory");
        __syncthreads();   // publishes A[s] (converted last iter); gates slot reuse

        if (s + 3 < NIT)
            issue_stage_agg(sb, adj, (s + 3) & 3, (s + 3) * BK, brow, bcol, tid);
        else
            asm volatile("cp.async.commit_group;" ::: "memory");

        // convert next chunk's A while this chunk's MMA runs
        if (s + 1 < NIT)
            convert_stage(smemc + ((s + 1) & 3) * ASTAGE, crow, chalf, cnt);

        const uint32_t sA = sb + (s & 3) * ASTAGE + I_TILE;
        const uint32_t sB = sA + A_TILE;

        #pragma unroll
        for (int ks = 0; ks < 2; ks++) {
            uint32_t a[4][4];
            #pragma unroll
            for (int mi = 0; mi < 4; mi++) {
                const uint32_t addr = sA +
                    (wm * 64 + mi * 16 + (g & 1) * 8 + r) * PITCHB +
                    ks * 32 + (g >> 1) * 16;
                ldsm4(a[mi][0], a[mi][1], a[mi][2], a[mi][3], addr);
            }
            uint32_t b[8][2];
            #pragma unroll
            for (int nj = 0; nj < 4; nj++) {
                uint32_t r0, r1, r2, r3;
                const uint32_t addr = sB +
                    (wn * 64 + nj * 16 + (g >> 1) * 8 + r) * PITCHB +
                    ks * 32 + (g & 1) * 16;
                ldsm4(r0, r1, r2, r3, addr);
                b[nj * 2][0] = r0;     b[nj * 2][1] = r1;
                b[nj * 2 + 1][0] = r2; b[nj * 2 + 1][1] = r3;
            }
            #pragma unroll
            for (int mi = 0; mi < 4; mi++)
                #pragma unroll
                for (int nb = 0; nb < 8; nb++)
                    mma_h(acc[mi][nb], a[mi], b[nb][0], b[nb][1]);
        }
    }
    asm volatile("cp.async.wait_group 0;" ::: "memory");

    // degree reduce: tid and tid^1 share a row
    cnt += __shfl_xor_sync(~0u, cnt, 1);
    if (chalf == 0) srecip[crow] = 1.0f / (float)max(cnt, 1);
    __syncthreads();

    // epilogue: scale by reciprocal degree -> single fp16
    #pragma unroll
    for (int mi = 0; mi < 4; mi++) {
        const int lr = wm * 64 + mi * 16 + (lane >> 2);
        const int r0 = brow + lr;
        const float rc0 = srecip[lr];
        const float rc1 = srecip[lr + 8];
        #pragma unroll
        for (int nb = 0; nb < 8; nb++) {
            const int col = bcol + wn * 64 + nb * 8 + (lane & 3) * 2;
            const size_t o0 = ((size_t)r0 * DIM + col) >> 1;
            const size_t o1 = ((size_t)(r0 + 8) * DIM + col) >> 1;
            ((uint32_t*)g_aggq)[o0] =
                pack_h2(acc[mi][nb][0] * rc0, acc[mi][nb][1] * rc0);
            ((uint32_t*)g_aggq)[o1] =
                pack_h2(acc[mi][nb][2] * rc1, acc[mi][nb][3] * rc1);
        }
    }
}

// ---------------------------------------------------------------------------
// K3: out = relu(x@A + agg@B + c); all operands single fp16 (1 product).
// 4-stage single-sync ring, 2 tiles/stage, 2 CTAs/SM.
// ---------------------------------------------------------------------------
#define OSTAGE (2 * TILEB)        // 20480 B
#define OUT_SMEM (4 * OSTAGE)     // 81920 B

__device__ __forceinline__ void issue_stage_out(uint32_t sb, int slot, int chunk,
                                                int brow, int bcol, int tid) {
    const int pass = chunk >> 4;
    const int k0 = (chunk & 15) * BK;
    const __half* __restrict__ Aq = pass ? g_aggq : g_xq;
    const __half* __restrict__ Bq = pass ? g_BTq : g_ATq;
    const uint32_t base = sb + slot * OSTAGE;
    #pragma unroll
    for (int h = 0; h < 2; h++) {
        const int id = tid + h * 256;
        const int row = id >> 2, cc = id & 3;
        const uint32_t so = row * PITCHB + cc * 16;
        cp16(base + so, Aq + (size_t)(brow + row) * DIM + k0 + cc * 8);
        cp16(base + TILEB + so, Bq + (size_t)(bcol + row) * DIM + k0 + cc * 8);
    }
    asm volatile("cp.async.commit_group;" ::: "memory");
}

__global__ void __launch_bounds__(256, 2) out_mma_kernel(float* __restrict__ out) {
    extern __shared__ char smem[];
    const uint32_t sb = smem_u32(smem);
    const int tid = threadIdx.x;
    const int lane = tid & 31, w = tid >> 5;
    const int wm = w & 3, wn = w >> 2;
    const int brow = blockIdx.y * 128;
    const int bcol = blockIdx.x * 128;
    const int g = lane >> 3, r = lane & 7;

    const int NIT = 32;
    issue_stage_out(sb, 0, 0, brow, bcol, tid);
    issue_stage_out(sb, 1, 1, brow, bcol, tid);
    issue_stage_out(sb, 2, 2, brow, bcol, tid);

    float acc[2][8][4] = {};

    for (int s = 0; s < NIT; s++) {
        asm volatile("cp.async.wait_group 2;" ::: "memory");
        __syncthreads();

        const uint32_t sA = sb + (s & 3) * OSTAGE;
        const uint32_t sB = sA + TILEB;

        #pragma unroll
        for (int ks = 0; ks < 2; ks++) {
            uint32_t a[2][4];
            #pragma unroll
            for (int mi = 0; mi < 2; mi++) {
                const uint32_t ro =
                    (wm * 32 + mi * 16 + (g & 1) * 8 + r) * PITCHB +
                    ks * 32 + (g >> 1) * 16;
                ldsm4(a[mi][0], a[mi][1], a[mi][2], a[mi][3], sA + ro);
            }
            #pragma unroll
            for (int nj = 0; nj < 4; nj++) {
                uint32_t r0, r1, r2, r3;
                const uint32_t addr = sB +
                    (wn * 64 + nj * 16 + (g >> 1) * 8 + r) * PITCHB +
                    ks * 32 + (g & 1) * 16;
                ldsm4(r0, r1, r2, r3, addr);
                #pragma unroll
                for (int mi = 0; mi < 2; mi++) {
                    mma_h(acc[mi][nj * 2], a[mi], r0, r1);
                    mma_h(acc[mi][nj * 2 + 1], a[mi], r2, r3);
                }
            }
        }
        if (s + 3 < NIT)
            issue_stage_out(sb, (s + 3) & 3, s + 3, brow, bcol, tid);
        else
            asm volatile("cp.async.commit_group;" ::: "memory");
    }
    asm volatile("cp.async.wait_group 0;" ::: "memory");

    #pragma unroll
    for (int mi = 0; mi < 2; mi++) {
        const int r0 = brow + wm * 32 + mi * 16 + (lane >> 2);
        #pragma unroll
        for (int ni = 0; ni < 8; ni++) {
            const int col = bcol + wn * 64 + ni * 8 + (lane & 3) * 2;
            const float c0 = g_c[col], c1 = g_c[col + 1];
            float2 v0 = make_float2(fmaxf(acc[mi][ni][0] + c0, 0.f),
                                    fmaxf(acc[mi][ni][1] + c1, 0.f));
            *(float2*)&out[(size_t)r0 * DIM + col] = v0;
            float2 v1 = make_float2(fmaxf(acc[mi][ni][2] + c0, 0.f),
                                    fmaxf(acc[mi][ni][3] + c1, 0.f));
            *(float2*)&out[(size_t)(r0 + 8) * DIM + col] = v1;
        }
    }
}

// ---------------------------------------------------------------------------
extern "C" void kernel_launch(void* const* d_in, const int* in_sizes, int n_in,
                              void* d_out, int out_size) {
    const float* x      = (const float*)d_in[0];
    const int*   adj    = (const int*)d_in[1];
    const float* W_self = (const float*)d_in[2];
    const float* b_self = (const float*)d_in[3];
    const float* W_nb   = (const float*)d_in[4];
    const float* b_nb   = (const float*)d_in[5];
    const float* W_comb = (const float*)d_in[6];
    const float* b_comb = (const float*)d_in[7];
    float* out = (float*)d_out;

    static bool attr_done = false;
    if (!attr_done) {
        cudaFuncSetAttribute(agg_mma_kernel,
                             cudaFuncAttributeMaxDynamicSharedMemorySize, AGG_SMEM);
        cudaFuncSetAttribute(out_mma_kernel,
                             cudaFuncAttributeMaxDynamicSharedMemorySize, OUT_SMEM);
        attr_done = true;
    }

    fuse_weights_kernel<<<dim3(8, 8, 2), 256>>>(W_self, W_nb, W_comb);
    fuse_bias_partial_kernel<<<16, 512>>>(b_self, b_nb, W_comb);
    fuse_bias_reduce_kernel<<<1, 512>>>(b_comb);
    transpose_split_kernel<<<dim3(DIM / 32, N_NODES / 32), dim3(32, 8)>>>(x);
    agg_mma_kernel<<<dim3(2, 64), 256, AGG_SMEM>>>(adj);
    out_mma_kernel<<<dim3(4, 64), 256, OUT_SMEM>>>(out);
}

// round 16
// speedup vs baseline: 1.1377x; 1.1377x over previous
#include <cuda_runtime.h>
#include <cuda_fp16.h>
#include <cstdint>

#define N_NODES 8192
#define DIM 512

// ---------------- scratch (__device__ globals; no allocs allowed) ----------
__device__ float g_c[DIM];                                    // fused bias
__device__ float g_cpart[16 * DIM];                           // bias partials
__device__ float g_recip[N_NODES];                            // 1/max(deg,1)
__device__ __align__(16) __half g_xTq[DIM * N_NODES];         // [feat][node]
__device__ __align__(16) __half g_xq[N_NODES * DIM];          // [node][feat]
__device__ __align__(16) __half g_aggq[N_NODES * DIM];        // [node][feat]
__device__ __align__(16) __half g_ATq[DIM * DIM];             // (W_self@Wt)^T
__device__ __align__(16) __half g_BTq[DIM * DIM];             // (W_nb@Wb)^T
__device__ __align__(16) __half g_mask[(size_t)N_NODES * N_NODES]; // {0,1}

// ---------------- PTX helpers ----------------------------------------------
__device__ __forceinline__ uint32_t smem_u32(const void* p) {
    uint32_t a;
    asm("{ .reg .u64 t; cvta.to.shared.u64 t, %1; cvt.u32.u64 %0, t; }"
        : "=r"(a) : "l"(p));
    return a;
}
__device__ __forceinline__ void cp16(uint32_t dst, const void* src) {
    asm volatile("cp.async.cg.shared.global [%0], [%1], 16;"
                 :: "r"(dst), "l"(src) : "memory");
}
__device__ __forceinline__ void ldsm4(uint32_t& r0, uint32_t& r1, uint32_t& r2,
                                      uint32_t& r3, uint32_t addr) {
    asm volatile("ldmatrix.sync.aligned.m8n8.x4.shared.b16 {%0,%1,%2,%3}, [%4];"
                 : "=r"(r0), "=r"(r1), "=r"(r2), "=r"(r3) : "r"(addr));
}
__device__ __forceinline__ void mma_h(float* d, const uint32_t* a,
                                      const uint32_t& b0, const uint32_t& b1) {
    asm volatile(
        "mma.sync.aligned.m16n8k16.row.col.f32.f16.f16.f32 "
        "{%0,%1,%2,%3}, {%4,%5,%6,%7}, {%8,%9}, {%0,%1,%2,%3};"
        : "+f"(d[0]), "+f"(d[1]), "+f"(d[2]), "+f"(d[3])
        : "r"(a[0]), "r"(a[1]), "r"(a[2]), "r"(a[3]), "r"(b0), "r"(b1));
}
__device__ __forceinline__ uint32_t pack_h2(float a, float b) {
    __half2 h = __floats2half2_rn(a, b);
    return *(uint32_t*)&h;
}

// ---------------------------------------------------------------------------
// K0a: fused weights -> transposed fp16 (B-operand layout)
// ---------------------------------------------------------------------------
__global__ void fuse_weights_kernel(const float* __restrict__ W_self,
                                    const float* __restrict__ W_nb,
                                    const float* __restrict__ W_comb) {
    const int z = blockIdx.z;
    const float* __restrict__ Wx = z ? W_nb : W_self;
    __half* __restrict__ oq = z ? g_BTq : g_ATq;
    const int woff = z * DIM;

    __shared__ float As[16][64];
    __shared__ float Bs[16][64];
    const int tid = threadIdx.x;
    const int tx = tid & 15, ty = tid >> 4;
    const int brow = blockIdx.y * 64, bcol = blockIdx.x * 64;
    const int a_m = tid >> 2, a_kc = (tid & 3) << 2;
    const int b_k = tid >> 4, b_n = (tid & 15) << 2;

    float acc[4][4] = {};
    for (int k0 = 0; k0 < DIM; k0 += 16) {
        float4 av = *(const float4*)&Wx[(brow + a_m) * DIM + k0 + a_kc];
        As[a_kc + 0][a_m] = av.x; As[a_kc + 1][a_m] = av.y;
        As[a_kc + 2][a_m] = av.z; As[a_kc + 3][a_m] = av.w;
        *(float4*)&Bs[b_k][b_n] =
            *(const float4*)&W_comb[(woff + k0 + b_k) * DIM + bcol + b_n];
        __syncthreads();
        #pragma unroll
        for (int k = 0; k < 16; k++) {
            float af[4], bf[4];
            *(float4*)af = *(const float4*)&As[k][ty * 4];
            *(float4*)bf = *(const float4*)&Bs[k][tx * 4];
            #pragma unroll
            for (int i = 0; i < 4; i++)
                #pragma unroll
                for (int j = 0; j < 4; j++) acc[i][j] += af[i] * bf[j];
        }
        __syncthreads();
    }
    #pragma unroll
    for (int i = 0; i < 4; i++) {
        const int k = brow + ty * 4 + i;
        #pragma unroll
        for (int j = 0; j < 4; j++) {
            const int n = bcol + tx * 4 + j;
            oq[n * DIM + k] = __float2half_rn(acc[i][j]);
        }
    }
}

// ---------------------------------------------------------------------------
// K0b: fused bias — parallel partials + reduce
// ---------------------------------------------------------------------------
__global__ void fuse_bias_partial_kernel(const float* __restrict__ b_self,
                                         const float* __restrict__ b_nb,
                                         const float* __restrict__ W_comb) {
    const int p = blockIdx.x;
    const int j = threadIdx.x;
    const int k0 = p * 32;
    float s0 = 0.f, s1 = 0.f;
    #pragma unroll 8
    for (int k = k0; k < k0 + 32; k++) {
        s0 += b_self[k] * W_comb[k * DIM + j];
        s1 += b_nb[k] * W_comb[(DIM + k) * DIM + j];
    }
    g_cpart[p * DIM + j] = s0 + s1;
}

__global__ void fuse_bias_reduce_kernel(const float* __restrict__ b_comb) {
    const int j = threadIdx.x;
    float s = b_comb[j];
    #pragma unroll
    for (int p = 0; p < 16; p++) s += g_cpart[p * DIM + j];
    g_c[j] = s;
}

// ---------------------------------------------------------------------------
// K1: degree -> reciprocal, fused with adj -> fp16 mask
// ---------------------------------------------------------------------------
__global__ void degree_mask_kernel(const int* __restrict__ adj) {
    const int row = blockIdx.x;
    const int4* __restrict__ p = (const int4*)(adj + (size_t)row * N_NODES);
    uint2* __restrict__ mrow = (uint2*)(g_mask + (size_t)row * N_NODES);
    int cnt = 0;
    for (int i = threadIdx.x; i < N_NODES / 4; i += blockDim.x) {
        int4 v = p[i];
        cnt += (v.x > 0) + (v.y > 0) + (v.z > 0) + (v.w > 0);
        uint2 o;
        o.x = (v.x > 0 ? 0x3C00u : 0u) | ((v.y > 0 ? 0x3C00u : 0u) << 16);
        o.y = (v.z > 0 ? 0x3C00u : 0u) | ((v.w > 0 ? 0x3C00u : 0u) << 16);
        mrow[i] = o;
    }
    #pragma unroll
    for (int o = 16; o; o >>= 1) cnt += __shfl_down_sync(0xffffffffu, cnt, o);
    __shared__ int wsum[8];
    if ((threadIdx.x & 31) == 0) wsum[threadIdx.x >> 5] = cnt;
    __syncthreads();
    if (threadIdx.x == 0) {
        int t = 0;
        #pragma unroll
        for (int w = 0; w < 8; w++) t += wsum[w];
        g_recip[row] = 1.0f / (float)max(t, 1);
    }
}

// ---------------------------------------------------------------------------
// K1b: x -> fp16 row-major + fp16 transposed
// ---------------------------------------------------------------------------
__global__ void transpose_split_kernel(const float* __restrict__ x) {
    __shared__ float t[32][33];
    const int c0 = blockIdx.x * 32;
    const int r0 = blockIdx.y * 32;
    const int tx = threadIdx.x, ty = threadIdx.y;
    #pragma unroll
    for (int i = 0; i < 4; i++) {
        const size_t gi = (size_t)(r0 + ty + 8 * i) * DIM + c0 + tx;
        float v = x[gi];
        t[ty + 8 * i][tx] = v;
        g_xq[gi] = __float2half_rn(v);
    }
    __syncthreads();
    #pragma unroll
    for (int i = 0; i < 4; i++) {
        float v = t[tx][ty + 8 * i];
        size_t o = (size_t)(c0 + ty + 8 * i) * N_NODES + r0 + tx;
        g_xTq[o] = __float2half_rn(v);
    }
}

// ---------------------------------------------------------------------------
// shared GEMM geometry
// ---------------------------------------------------------------------------
#define BK 32
#define PITCHB 80
#define TILEB (128 * PITCHB)      // 10240 B (128-row fp16 tile)

// ---------------------------------------------------------------------------
// K2: agg = (mask @ x) * recip  via fp16 HMMA, 64x64 warp tiles.
// BM=128, BN=256, 8 warps (2M x 4N), 4-stage single-sync ring.  (R12 exact)
// ---------------------------------------------------------------------------
#define A_TILE (128 * PITCHB)     // 10240 B
#define B_TILE (256 * PITCHB)     // 20480 B
#define ASTAGE (A_TILE + B_TILE)  // 30720 B
#define AGG_SMEM (4 * ASTAGE)     // 122880 B

__device__ __forceinline__ void issue_stage_agg(uint32_t sb, int slot, int k0,
                                                int brow, int bcol, int tid) {
    const uint32_t base = sb + slot * ASTAGE;
    #pragma unroll
    for (int h = 0; h < 6; h++) {
        const int id = tid + h * 256;         // 0..1535
        if (id < 512) {                       // A: 128 rows x 4 quads
            const int row = id >> 2, cc = id & 3;
            cp16(base + row * PITCHB + cc * 16,
                 g_mask + (size_t)(brow + row) * N_NODES + k0 + cc * 8);
        } else {                              // B: 256 rows x 4 quads
            const int bid = id - 512;
            const int row = bid >> 2, cc = bid & 3;
            cp16(base + A_TILE + row * PITCHB + cc * 16,
                 g_xTq + (size_t)(bcol + row) * N_NODES + k0 + cc * 8);
        }
    }
    asm volatile("cp.async.commit_group;" ::: "memory");
}

__global__ void __launch_bounds__(256, 1) agg_mma_kernel() {
    extern __shared__ char smem[];
    const uint32_t sb = smem_u32(smem);
    const int tid = threadIdx.x;
    const int lane = tid & 31, w = tid >> 5;
    const int wm = w & 1, wn = w >> 1;        // 2M x 4N warps, 64x64 each
    const int brow = blockIdx.y * 128;
    const int bcol = blockIdx.x * 256;
    const int g = lane >> 3, r = lane & 7;

    const int NIT = N_NODES / BK;  // 256
    issue_stage_agg(sb, 0, 0, brow, bcol, tid);
    issue_stage_agg(sb, 1, BK, brow, bcol, tid);
    issue_stage_agg(sb, 2, 2 * BK, brow, bcol, tid);

    float acc[4][8][4] = {};   // 4 m16 x 8 n8

    for (int s = 0; s < NIT; s++) {
        asm volatile("cp.async.wait_group 2;" ::: "memory");
        __syncthreads();

        const uint32_t sA = sb + (s & 3) * ASTAGE;
        const uint32_t sB = sA + A_TILE;

        #pragma unroll
        for (int ks = 0; ks < 2; ks++) {
            uint32_t a[4][4];
            #pragma unroll
            for (int mi = 0; mi < 4; mi++) {
                const uint32_t addr = sA +
                    (wm * 64 + mi * 16 + (g & 1) * 8 + r) * PITCHB +
                    ks * 32 + (g >> 1) * 16;
                ldsm4(a[mi][0], a[mi][1], a[mi][2], a[mi][3], addr);
            }
            uint32_t b[8][2];
            #pragma unroll
            for (int nj = 0; nj < 4; nj++) {
                uint32_t r0, r1, r2, r3;
                const uint32_t addr = sB +
                    (wn * 64 + nj * 16 + (g >> 1) * 8 + r) * PITCHB +
                    ks * 32 + (g & 1) * 16;
                ldsm4(r0, r1, r2, r3, addr);
                b[nj * 2][0] = r0;     b[nj * 2][1] = r1;
                b[nj * 2 + 1][0] = r2; b[nj * 2 + 1][1] = r3;
            }
            #pragma unroll
            for (int mi = 0; mi < 4; mi++)
                #pragma unroll
                for (int nb = 0; nb < 8; nb++)
                    mma_h(acc[mi][nb], a[mi], b[nb][0], b[nb][1]);
        }
        if (s + 3 < NIT)
            issue_stage_agg(sb, (s + 3) & 3, (s + 3) * BK, brow, bcol, tid);
        else
            asm volatile("cp.async.commit_group;" ::: "memory");
    }
    asm volatile("cp.async.wait_group 0;" ::: "memory");

    // epilogue: scale by reciprocal degree -> single fp16
    #pragma unroll
    for (int mi = 0; mi < 4; mi++) {
        const int r0 = brow + wm * 64 + mi * 16 + (lane >> 2);
        const float rc0 = g_recip[r0];
        const float rc1 = g_recip[r0 + 8];
        #pragma unroll
        for (int nb = 0; nb < 8; nb++) {
            const int col = bcol + wn * 64 + nb * 8 + (lane & 3) * 2;
            const size_t o0 = ((size_t)r0 * DIM + col) >> 1;
            const size_t o1 = ((size_t)(r0 + 8) * DIM + col) >> 1;
            ((uint32_t*)g_aggq)[o0] =
                pack_h2(acc[mi][nb][0] * rc0, acc[mi][nb][1] * rc0);
            ((uint32_t*)g_aggq)[o1] =
                pack_h2(acc[mi][nb][2] * rc1, acc[mi][nb][3] * rc1);
        }
    }
}

// ---------------------------------------------------------------------------
// K3: out = relu(x@A + agg@B + c); all operands single fp16 (1 product).
// 4-stage single-sync ring, 2 tiles/stage, 2 CTAs/SM.  (R12 exact)
// ---------------------------------------------------------------------------
#define OSTAGE (2 * TILEB)        // 20480 B
#define OUT_SMEM (4 * OSTAGE)     // 81920 B

__device__ __forceinline__ void issue_stage_out(uint32_t sb, int slot, int chunk,
                                                int brow, int bcol, int tid) {
    const int pass = chunk >> 4;
    const int k0 = (chunk & 15) * BK;
    const __half* __restrict__ Aq = pass ? g_aggq : g_xq;
    const __half* __restrict__ Bq = pass ? g_BTq : g_ATq;
    const uint32_t base = sb + slot * OSTAGE;
    #pragma unroll
    for (int h = 0; h < 2; h++) {
        const int id = tid + h * 256;
        const int row = id >> 2, cc = id & 3;
        const uint32_t so = row * PITCHB + cc * 16;
        cp16(base + so, Aq + (size_t)(brow + row) * DIM + k0 + cc * 8);
        cp16(base + TILEB + so, Bq + (size_t)(bcol + row) * DIM + k0 + cc * 8);
    }
    asm volatile("cp.async.commit_group;" ::: "memory");
}

__global__ void __launch_bounds__(256, 2) out_mma_kernel(float* __restrict__ out) {
    extern __shared__ char smem[];
    const uint32_t sb = smem_u32(smem);
    const int tid = threadIdx.x;
    const int lane = tid & 31, w = tid >> 5;
    const int wm = w & 3, wn = w >> 2;
    const int brow = blockIdx.y * 128;
    const int bcol = blockIdx.x * 128;
    const int g = lane >> 3, r = lane & 7;

    const int NIT = 32;
    issue_stage_out(sb, 0, 0, brow, bcol, tid);
    issue_stage_out(sb, 1, 1, brow, bcol, tid);
    issue_stage_out(sb, 2, 2, brow, bcol, tid);

    float acc[2][8][4] = {};

    for (int s = 0; s < NIT; s++) {
        asm volatile("cp.async.wait_group 2;" ::: "memory");
        __syncthreads();

        const uint32_t sA = sb + (s & 3) * OSTAGE;
        const uint32_t sB = sA + TILEB;

        #pragma unroll
        for (int ks = 0; ks < 2; ks++) {
            uint32_t a[2][4];
            #pragma unroll
            for (int mi = 0; mi < 2; mi++) {
                const uint32_t ro =
                    (wm * 32 + mi * 16 + (g & 1) * 8 + r) * PITCHB +
                    ks * 32 + (g >> 1) * 16;
                ldsm4(a[mi][0], a[mi][1], a[mi][2], a[mi][3], sA + ro);
            }
            #pragma unroll
            for (int nj = 0; nj < 4; nj++) {
                uint32_t r0, r1, r2, r3;
                const uint32_t addr = sB +
                    (wn * 64 + nj * 16 + (g >> 1) * 8 + r) * PITCHB +
                    ks * 32 + (g & 1) * 16;
                ldsm4(r0, r1, r2, r3, addr);
                #pragma unroll
                for (int mi = 0; mi < 2; mi++) {
                    mma_h(acc[mi][nj * 2], a[mi], r0, r1);
                    mma_h(acc[mi][nj * 2 + 1], a[mi], r2, r3);
                }
            }
        }
        if (s + 3 < NIT)
            issue_stage_out(sb, (s + 3) & 3, s + 3, brow, bcol, tid);
        else
            asm volatile("cp.async.commit_group;" ::: "memory");
    }
    asm volatile("cp.async.wait_group 0;" ::: "memory");

    #pragma unroll
    for (int mi = 0; mi < 2; mi++) {
        const int r0 = brow + wm * 32 + mi * 16 + (lane >> 2);
        #pragma unroll
        for (int ni = 0; ni < 8; ni++) {
            const int col = bcol + wn * 64 + ni * 8 + (lane & 3) * 2;
            const float c0 = g_c[col], c1 = g_c[col + 1];
            float2 v0 = make_float2(fmaxf(acc[mi][ni][0] + c0, 0.f),
                                    fmaxf(acc[mi][ni][1] + c1, 0.f));
            *(float2*)&out[(size_t)r0 * DIM + col] = v0;
            float2 v1 = make_float2(fmaxf(acc[mi][ni][2] + c0, 0.f),
                                    fmaxf(acc[mi][ni][3] + c1, 0.f));
            *(float2*)&out[(size_t)(r0 + 8) * DIM + col] = v1;
        }
    }
}

// ---------------------------------------------------------------------------
extern "C" void kernel_launch(void* const* d_in, const int* in_sizes, int n_in,
                              void* d_out, int out_size) {
    const float* x      = (const float*)d_in[0];
    const int*   adj    = (const int*)d_in[1];
    const float* W_self = (const float*)d_in[2];
    const float* b_self = (const float*)d_in[3];
    const float* W_nb   = (const float*)d_in[4];
    const float* b_nb   = (const float*)d_in[5];
    const float* W_comb = (const float*)d_in[6];
    const float* b_comb = (const float*)d_in[7];
    float* out = (float*)d_out;

    static cudaStream_t s2 = nullptr;
    static cudaEvent_t evRoot = nullptr, evT = nullptr, evW = nullptr;
    static bool attr_done = false;
    if (!attr_done) {
        cudaFuncSetAttribute(agg_mma_kernel,
                             cudaFuncAttributeMaxDynamicSharedMemorySize, AGG_SMEM);
        cudaFuncSetAttribute(out_mma_kernel,
                             cudaFuncAttributeMaxDynamicSharedMemorySize, OUT_SMEM);
        cudaStreamCreateWithFlags(&s2, cudaStreamNonBlocking);
        cudaEventCreateWithFlags(&evRoot, cudaEventDisableTiming);
        cudaEventCreateWithFlags(&evT, cudaEventDisableTiming);
        cudaEventCreateWithFlags(&evW, cudaEventDisableTiming);
        attr_done = true;
    }

    // fork: side chain (transpose + weights + bias) on s2
    cudaEventRecord(evRoot, 0);
    cudaStreamWaitEvent(s2, evRoot, 0);
    transpose_split_kernel<<<dim3(DIM / 32, N_NODES / 32), dim3(32, 8), 0, s2>>>(x);
    cudaEventRecord(evT, s2);
    fuse_weights_kernel<<<dim3(8, 8, 2), 256, 0, s2>>>(W_self, W_nb, W_comb);
    fuse_bias_partial_kernel<<<16, 512, 0, s2>>>(b_self, b_nb, W_comb);
    fuse_bias_reduce_kernel<<<1, 512, 0, s2>>>(b_comb);
    cudaEventRecord(evW, s2);

    // main chain: degree_mask runs concurrently with the side chain
    degree_mask_kernel<<<N_NODES, 256>>>(adj);
    cudaStreamWaitEvent(0, evT, 0);     // agg needs xTq
    agg_mma_kernel<<<dim3(2, 64), 256, AGG_SMEM>>>();
    cudaStreamWaitEvent(0, evW, 0);     // out needs weights + bias
    out_mma_kernel<<<dim3(4, 64), 256, OUT_SMEM>>>(out);
}